// round 13
// baseline (speedup 1.0000x reference)
#include <cuda_runtime.h>
#include <cuda_bf16.h>
#include <math.h>
#include <stdint.h>

// Problem constants
#define BATCH 2
#define SEQ   2048
#define DMODEL 2048
#define NHEADS 16
#define DK 128
#define DV 128
#define MROWS (BATCH*SEQ)           // 4096
#define SCALE 0.08838834764831845f  // 1/sqrt(128)
#define KV_SPLITS 4

// ---------------- scratch (device globals; no allocations allowed) ------------
__device__ float g_q[(size_t)MROWS * NHEADS * DK];    // [B*S, H*DK]  (tf32-rounded)
__device__ float g_kv[(size_t)MROWS * 256];           // [B*S, K|V]   (tf32-rounded)
__device__ float g_attn[(size_t)MROWS * NHEADS * DV]; // [B*S, H*DV]
__device__ float g_part[(size_t)KV_SPLITS * MROWS * 256]; // split-K partials
__device__ float g_zero[128];                         // zero bias (static-init 0)
__device__ float2 g_ropetab[SEQ * 64];                // (cos, sin)

// ---------------- helpers ----------------------------------------------------
__device__ __forceinline__ uint32_t f2tf(float x) {
    uint32_t u;
    asm("cvt.rna.tf32.f32 %0, %1;" : "=r"(u) : "f"(x));
    return u;
}
__device__ __forceinline__ float f2tf_f(float x) {
    return __uint_as_float(f2tf(x));
}
__device__ __forceinline__ void mma_tf32(float* d, const uint32_t* a,
                                         uint32_t b0, uint32_t b1) {
    asm volatile(
        "mma.sync.aligned.m16n8k8.row.col.f32.tf32.tf32.f32 "
        "{%0,%1,%2,%3}, {%4,%5,%6,%7}, {%8,%9}, {%0,%1,%2,%3};"
        : "+f"(d[0]), "+f"(d[1]), "+f"(d[2]), "+f"(d[3])
        : "r"(a[0]), "r"(a[1]), "r"(a[2]), "r"(a[3]), "r"(b0), "r"(b1));
}
__device__ __forceinline__ uint32_t smem_u32(const void* p) {
    uint32_t a;
    asm("{ .reg .u64 t; cvta.to.shared.u64 t, %1; cvt.u32.u64 %0, t; }" : "=r"(a) : "l"(p));
    return a;
}
__device__ __forceinline__ void cp_async16(uint32_t dst, const void* src) {
    asm volatile("cp.async.cg.shared.global [%0], [%1], 16;" :: "r"(dst), "l"(src));
}
__device__ __forceinline__ void cp_commit() {
    asm volatile("cp.async.commit_group;");
}
template<int N>
__device__ __forceinline__ void cp_wait() {
    asm volatile("cp.async.wait_group %0;" :: "n"(N));
}

// ---------------- rope table --------------------------------------------------
__global__ void rope_table_kernel()
{
    int idx = blockIdx.x * blockDim.x + threadIdx.x;
    if (idx >= SEQ * 64) return;
    int s = idx >> 6, j = idx & 63;
    float inv = powf(10000.f, -(float)j / 64.f);
    float sn, cs;
    sincosf((float)s * inv, &sn, &cs);
    g_ropetab[idx] = make_float2(cs, sn);
}

// ---------------- mma.sync tf32 GEMM core -------------------------------------
// BM=128, BN=128, BK=32, 256 threads (8 warps, 4m x 2n), warp tile 32x64.
// A is [M,K] row-major (K-major smem, stride 36).
// B is [K,N] row-major, read directly (no transpose); smem [32][136].
// If ROPE: epilogue stages tile in smem, applies RoPE, stores tf32-rounded.
#define AS_STAGE 4608               // 128*36
#define BS_STAGE 4352               // 32*136
#define GEMM_SMEM ((2*AS_STAGE + 2*BS_STAGE) * 4)   // 71680 B (rope needs 128*129*4=66048, fits)

template<bool ROPE>
__device__ __forceinline__ void gemm_core(
    const float* __restrict__ A, int lda,
    const float* __restrict__ B, int ldb,
    const float* __restrict__ bias, float* __restrict__ C, int ldc,
    int m0, int n0, int klen, uint32_t* sm)
{
    uint32_t* As = sm;                       // [2][128][36]
    uint32_t* Bs = sm + 2 * AS_STAGE;        // [2][32][136]

    const int tid = threadIdx.x;
    const int wid = tid >> 5, lane = tid & 31;
    const int g = lane >> 2, t = lane & 3;
    const int warpM = wid & 3, warpN = wid >> 2;
    const int NI = klen >> 5;

    float acc[2][8][4] = {};
    float4 pa[4], pb[4];

    // prologue: stage 0
    {
        const float* Ag = A + (size_t)m0 * lda;
        const float* Bg = B + n0;
        #pragma unroll
        for (int s = 0; s < 4; s++) {
            int idx = tid + s * 256;
            pa[s] = *(const float4*)(Ag + (size_t)(idx >> 3) * lda + (idx & 7) * 4);
            pb[s] = *(const float4*)(Bg + (size_t)(idx >> 5) * ldb + (idx & 31) * 4);
        }
        #pragma unroll
        for (int s = 0; s < 4; s++) {
            int idx = tid + s * 256;
            uint4 ua = make_uint4(f2tf(pa[s].x), f2tf(pa[s].y), f2tf(pa[s].z), f2tf(pa[s].w));
            uint4 ub = make_uint4(f2tf(pb[s].x), f2tf(pb[s].y), f2tf(pb[s].z), f2tf(pb[s].w));
            *(uint4*)(As + (idx >> 3) * 36 + (idx & 7) * 4) = ua;
            *(uint4*)(Bs + (idx >> 5) * 136 + (idx & 31) * 4) = ub;
        }
    }
    __syncthreads();

    for (int it = 0; it < NI; it++) {
        const int buf = it & 1;
        if (it + 1 < NI) {
            const float* Ag = A + (size_t)m0 * lda + (it + 1) * 32;
            const float* Bg = B + (size_t)((it + 1) * 32) * ldb + n0;
            #pragma unroll
            for (int s = 0; s < 4; s++) {
                int idx = tid + s * 256;
                pa[s] = *(const float4*)(Ag + (size_t)(idx >> 3) * lda + (idx & 7) * 4);
                pb[s] = *(const float4*)(Bg + (size_t)(idx >> 5) * ldb + (idx & 31) * 4);
            }
        }

        const uint32_t* Abuf = As + buf * AS_STAGE + warpM * 32 * 36;
        const uint32_t* Bbuf = Bs + buf * BS_STAGE + warpN * 64;
        #pragma unroll
        for (int kk = 0; kk < 4; kk++) {
            uint32_t af[2][4], bf[8][2];
            #pragma unroll
            for (int mi = 0; mi < 2; mi++) {
                const uint32_t* p = Abuf + (mi * 16 + g) * 36 + kk * 8 + t;
                af[mi][0] = p[0];
                af[mi][1] = p[8 * 36];
                af[mi][2] = p[4];
                af[mi][3] = p[8 * 36 + 4];
            }
            #pragma unroll
            for (int ni = 0; ni < 8; ni++) {
                const uint32_t* p = Bbuf + (kk * 8 + t) * 136 + ni * 8 + g;
                bf[ni][0] = p[0];
                bf[ni][1] = p[4 * 136];
            }
            #pragma unroll
            for (int mi = 0; mi < 2; mi++)
                #pragma unroll
                for (int ni = 0; ni < 8; ni++)
                    mma_tf32(acc[mi][ni], af[mi], bf[ni][0], bf[ni][1]);
        }

        if (it + 1 < NI) {
            uint32_t* Ad = As + (buf ^ 1) * AS_STAGE;
            uint32_t* Bd = Bs + (buf ^ 1) * BS_STAGE;
            #pragma unroll
            for (int s = 0; s < 4; s++) {
                int idx = tid + s * 256;
                uint4 ua = make_uint4(f2tf(pa[s].x), f2tf(pa[s].y), f2tf(pa[s].z), f2tf(pa[s].w));
                uint4 ub = make_uint4(f2tf(pb[s].x), f2tf(pb[s].y), f2tf(pb[s].z), f2tf(pb[s].w));
                *(uint4*)(Ad + (idx >> 3) * 36 + (idx & 7) * 4) = ua;
                *(uint4*)(Bd + (idx >> 5) * 136 + (idx & 31) * 4) = ub;
            }
        }
        __syncthreads();
    }

    if (!ROPE) {
        // epilogue: bias + store
        #pragma unroll
        for (int mi = 0; mi < 2; mi++) {
            int r0 = m0 + warpM * 32 + mi * 16 + g;
            #pragma unroll
            for (int ni = 0; ni < 8; ni++) {
                int col = n0 + warpN * 64 + ni * 8 + 2 * t;
                float b0 = bias[col], b1 = bias[col + 1];
                *(float2*)(C + (size_t)r0 * ldc + col) =
                    make_float2(acc[mi][ni][0] + b0, acc[mi][ni][1] + b1);
                *(float2*)(C + (size_t)(r0 + 8) * ldc + col) =
                    make_float2(acc[mi][ni][2] + b0, acc[mi][ni][3] + b1);
            }
        }
    } else {
        // fused RoPE epilogue (one head per N-tile); output tf32-rounded for flash
        float* Ssm = (float*)sm;   // [128][129]
        #pragma unroll
        for (int mi = 0; mi < 2; mi++) {
            int rl = warpM * 32 + mi * 16 + g;
            #pragma unroll
            for (int ni = 0; ni < 8; ni++) {
                int cl = warpN * 64 + ni * 8 + 2 * t;
                float b0 = bias[n0 + cl], b1 = bias[n0 + cl + 1];
                Ssm[rl * 129 + cl]           = acc[mi][ni][0] + b0;
                Ssm[rl * 129 + cl + 1]       = acc[mi][ni][1] + b1;
                Ssm[(rl + 8) * 129 + cl]     = acc[mi][ni][2] + b0;
                Ssm[(rl + 8) * 129 + cl + 1] = acc[mi][ni][3] + b1;
            }
        }
        __syncthreads();
        for (int i = tid; i < 128 * 64; i += 256) {
            int r = i >> 6, j = i & 63;
            int grow = m0 + r;
            int s = grow & (SEQ - 1);
            float2 cs = g_ropetab[s * 64 + j];
            float x1 = Ssm[r * 129 + j];
            float x2 = Ssm[r * 129 + j + 64];
            C[(size_t)grow * ldc + n0 + j]      = f2tf_f(x1 * cs.x - x2 * cs.y);
            C[(size_t)grow * ldc + n0 + j + 64] = f2tf_f(x1 * cs.y + x2 * cs.x);
        }
    }
}

template<bool ROPE>
__global__ __launch_bounds__(256) void gemm_kernel(
    const float* __restrict__ A, int lda,
    const float* __restrict__ B, int ldb,
    const float* __restrict__ bias, float* __restrict__ C, int ldc, int klen)
{
    extern __shared__ uint32_t sm[];
    gemm_core<ROPE>(A, lda, B, ldb, bias, C, ldc,
                    blockIdx.y * 128, blockIdx.x * 128, klen, sm);
}

// KV projection, split-K: bx selects K(0)/V(1), bz selects K-chunk of 512.
__global__ __launch_bounds__(256) void kv_split_kernel(
    const float* __restrict__ k_in, const float* __restrict__ v_in,
    const float* __restrict__ Wk, const float* __restrict__ Wv)
{
    extern __shared__ uint32_t sm[];
    const int bx = blockIdx.x;            // 0 = K, 1 = V
    const int z  = blockIdx.z;            // K-split
    const float* A = (bx ? v_in : k_in) + z * (DMODEL / KV_SPLITS);
    const float* B = (bx ? Wv : Wk) + (size_t)(z * (DMODEL / KV_SPLITS)) * DK;
    float* C = g_part + (size_t)z * MROWS * 256 + bx * 128;
    gemm_core<false>(A, DMODEL, B, DK, g_zero, C, 256,
                     blockIdx.y * 128, 0, DMODEL / KV_SPLITS, sm);
}

// Reduce split-K partials (K half): bias + K-RoPE; store tf32-rounded.
__global__ void kv_reduce_k_kernel(const float* __restrict__ bk)
{
    int idx = blockIdx.x * blockDim.x + threadIdx.x;
    if (idx >= MROWS * 64) return;
    int row = idx >> 6, j = idx & 63;
    float s0 = 0.f, s1 = 0.f;
    #pragma unroll
    for (int z = 0; z < KV_SPLITS; z++) {
        const float* p = g_part + ((size_t)z * MROWS + row) * 256;
        s0 += p[j];
        s1 += p[j + 64];
    }
    s0 += bk[j];
    s1 += bk[j + 64];
    int s = row & (SEQ - 1);
    float2 cs = g_ropetab[s * 64 + j];
    g_kv[(size_t)row * 256 + j]      = f2tf_f(s0 * cs.x - s1 * cs.y);
    g_kv[(size_t)row * 256 + j + 64] = f2tf_f(s0 * cs.y + s1 * cs.x);
}

// Reduce split-K partials (V half): bias; store tf32-rounded.
__global__ void kv_reduce_v_kernel(const float* __restrict__ bv)
{
    int idx = blockIdx.x * blockDim.x + threadIdx.x;
    if (idx >= MROWS * 128) return;
    int row = idx >> 7, c = idx & 127;
    float s0 = 0.f;
    #pragma unroll
    for (int z = 0; z < KV_SPLITS; z++)
        s0 += g_part[((size_t)z * MROWS + row) * 256 + 128 + c];
    g_kv[(size_t)row * 256 + 128 + c] = f2tf_f(s0 + bv[c]);
}

// ---------------- Flash attention (mma.sync tf32, causal, MQA) ----------------
// grid (16 qtiles, 16 h, 2 b), 256 threads. BQ=128, BKV=64.
// smem words: Ks[2][64][132] | Vs[2][64][136] | Ps[128][68]
// Q staging [128][132] overlaps the Ks region. cp.async double-buffered K/V.
#define KS_STRIDE 132
#define VS_STRIDE 136
#define KS_BUF (64 * KS_STRIDE)
#define VS_BUF (64 * VS_STRIDE)
#define FA_SMEM ((2 * KS_BUF + 2 * VS_BUF + 128 * 68) * 4)   // 172032 B

__global__ __launch_bounds__(256, 1) void flash_mma_kernel()
{
    extern __shared__ uint32_t fsm[];
    uint32_t* Ks2 = fsm;                       // 2 buffers
    uint32_t* Vs2 = fsm + 2 * KS_BUF;          // 2 buffers
    uint32_t* Ps  = fsm + 2 * KS_BUF + 2 * VS_BUF;  // [128][68]
    uint32_t* Qs  = fsm;                       // [128][132] staging (overlaps Ks2)

    const int qt = (int)gridDim.x - 1 - (int)blockIdx.x;  // heavy tiles first
    const int h  = blockIdx.y;
    const int b  = blockIdx.z;
    const int tid = threadIdx.x;
    const int wid = tid >> 5, lane = tid & 31;
    const int g = lane >> 2, t = lane & 3;
    const uint32_t smb = smem_u32(fsm);

    // stage Q tile (already tf32-rounded in g_q) and extract per-warp fragments
    for (int i = tid; i < 128 * 32; i += 256) {
        int r = i >> 5, c4 = i & 31;
        uint4 v = *(const uint4*)(g_q + (size_t)(b * SEQ + qt * 128 + r) * (NHEADS * DK)
                                      + h * DK + c4 * 4);
        *(uint4*)(Qs + r * KS_STRIDE + c4 * 4) = v;
    }
    __syncthreads();

    uint32_t qa[16][4];
    {
        const uint32_t* base = Qs + (wid * 16 + g) * KS_STRIDE;
        #pragma unroll
        for (int kk = 0; kk < 16; kk++) {
            qa[kk][0] = base[kk * 8 + t];
            qa[kk][1] = base[8 * KS_STRIDE + kk * 8 + t];
            qa[kk][2] = base[kk * 8 + t + 4];
            qa[kk][3] = base[8 * KS_STRIDE + kk * 8 + t + 4];
        }
    }
    __syncthreads();  // done with Qs before Ks2 overwrite

    const int nkt = 2 * qt + 2;

    // prefetch tile 0 into buffer 0
    {
        const float* src = g_kv + (size_t)(b * SEQ) * 256;
        uint32_t kdst = smb;                       // Ks2 buf0
        uint32_t vdst = smb + 2 * KS_BUF * 4;      // Vs2 buf0
        #pragma unroll
        for (int i = tid; i < 2048; i += 256) {
            int r = i >> 5, c4 = i & 31;
            cp_async16(kdst + (r * KS_STRIDE + c4 * 4) * 4, src + r * 256 + c4 * 4);
            cp_async16(vdst + (r * VS_STRIDE + c4 * 4) * 4, src + r * 256 + 128 + c4 * 4);
        }
        cp_commit();
    }

    float oacc[16][4] = {};
    float m0r = -INFINITY, m1r = -INFINITY, l0 = 0.f, l1 = 0.f;
    const int qrow0 = qt * 128 + wid * 16 + g;
    const int wmax  = qt * 128 + wid * 16 + 15;  // warp's last q row

    for (int kt = 0; kt < nkt; kt++) {
        const int buf = kt & 1;
        // prefetch tile kt+1 into the other buffer
        if (kt + 1 < nkt) {
            const float* src = g_kv + (size_t)(b * SEQ + (kt + 1) * 64) * 256;
            uint32_t kdst = smb + (buf ^ 1) * KS_BUF * 4;
            uint32_t vdst = smb + (2 * KS_BUF + (buf ^ 1) * VS_BUF) * 4;
            #pragma unroll
            for (int i = tid; i < 2048; i += 256) {
                int r = i >> 5, c4 = i & 31;
                cp_async16(kdst + (r * KS_STRIDE + c4 * 4) * 4, src + r * 256 + c4 * 4);
                cp_async16(vdst + (r * VS_STRIDE + c4 * 4) * 4, src + r * 256 + 128 + c4 * 4);
            }
            cp_commit();
            cp_wait<1>();   // tile kt's group done (kt+1 may remain in flight)
        } else {
            cp_wait<0>();
        }
        __syncthreads();

        const uint32_t* Ksb = Ks2 + buf * KS_BUF;
        const uint32_t* Vsb = Vs2 + buf * VS_BUF;
        const int kvb = kt * 64;
        if (kvb <= wmax) {   // warp-uniform: skip fully-masked warp tiles
            // S = Q K^T  (warp: 16 q rows x 64 kv)
            float s[8][4] = {};
            #pragma unroll
            for (int kk = 0; kk < 16; kk++) {
                uint32_t bf[8][2];
                #pragma unroll
                for (int ni = 0; ni < 8; ni++) {
                    const uint32_t* p = Ksb + (ni * 8 + g) * KS_STRIDE + kk * 8 + t;
                    bf[ni][0] = p[0];
                    bf[ni][1] = p[4];
                }
                #pragma unroll
                for (int ni = 0; ni < 8; ni++)
                    mma_tf32(s[ni], qa[kk], bf[ni][0], bf[ni][1]);
            }

            // scale + causal mask
            #pragma unroll
            for (int ni = 0; ni < 8; ni++) {
                int kv0 = kvb + ni * 8 + 2 * t;
                s[ni][0] = (kv0     > qrow0)     ? -INFINITY : s[ni][0] * SCALE;
                s[ni][1] = (kv0 + 1 > qrow0)     ? -INFINITY : s[ni][1] * SCALE;
                s[ni][2] = (kv0     > qrow0 + 8) ? -INFINITY : s[ni][2] * SCALE;
                s[ni][3] = (kv0 + 1 > qrow0 + 8) ? -INFINITY : s[ni][3] * SCALE;
            }

            // online softmax (rows g and g+8; 4-lane groups share a row)
            float mx0 = -INFINITY, mx1 = -INFINITY;
            #pragma unroll
            for (int ni = 0; ni < 8; ni++) {
                mx0 = fmaxf(mx0, fmaxf(s[ni][0], s[ni][1]));
                mx1 = fmaxf(mx1, fmaxf(s[ni][2], s[ni][3]));
            }
            mx0 = fmaxf(mx0, __shfl_xor_sync(0xffffffffu, mx0, 1));
            mx0 = fmaxf(mx0, __shfl_xor_sync(0xffffffffu, mx0, 2));
            mx1 = fmaxf(mx1, __shfl_xor_sync(0xffffffffu, mx1, 1));
            mx1 = fmaxf(mx1, __shfl_xor_sync(0xffffffffu, mx1, 2));
            float mn0 = fmaxf(m0r, mx0), mn1 = fmaxf(m1r, mx1);
            float c0 = __expf(m0r - mn0), c1 = __expf(m1r - mn1);
            m0r = mn0; m1r = mn1;

            float rs0 = 0.f, rs1 = 0.f;
            uint32_t* prow0 = Ps + (wid * 16 + g) * 68;
            uint32_t* prow1 = prow0 + 8 * 68;
            #pragma unroll
            for (int ni = 0; ni < 8; ni++) {
                float p0 = __expf(s[ni][0] - mn0);
                float p1 = __expf(s[ni][1] - mn0);
                float p2 = __expf(s[ni][2] - mn1);
                float p3 = __expf(s[ni][3] - mn1);
                rs0 += p0 + p1;
                rs1 += p2 + p3;
                prow0[ni * 8 + 2 * t]     = f2tf(p0);
                prow0[ni * 8 + 2 * t + 1] = f2tf(p1);
                prow1[ni * 8 + 2 * t]     = f2tf(p2);
                prow1[ni * 8 + 2 * t + 1] = f2tf(p3);
            }
            rs0 += __shfl_xor_sync(0xffffffffu, rs0, 1);
            rs0 += __shfl_xor_sync(0xffffffffu, rs0, 2);
            rs1 += __shfl_xor_sync(0xffffffffu, rs1, 1);
            rs1 += __shfl_xor_sync(0xffffffffu, rs1, 2);
            l0 = l0 * c0 + rs0;
            l1 = l1 * c1 + rs1;
            #pragma unroll
            for (int ni = 0; ni < 16; ni++) {
                oacc[ni][0] *= c0; oacc[ni][1] *= c0;
                oacc[ni][2] *= c1; oacc[ni][3] *= c1;
            }
            __syncwarp();  // P rows warp-private; order STS before cross-lane LDS

            // O += P V  (Vs stride 136 -> bank (8t+g): conflict-free)
            #pragma unroll
            for (int kk = 0; kk < 8; kk++) {
                uint32_t pf[4];
                const uint32_t* pp = Ps + (wid * 16 + g) * 68 + kk * 8 + t;
                pf[0] = pp[0];
                pf[1] = pp[8 * 68];
                pf[2] = pp[4];
                pf[3] = pp[8 * 68 + 4];
                #pragma unroll
                for (int ni = 0; ni < 16; ni++) {
                    const uint32_t* vp = Vsb + (kk * 8 + t) * VS_STRIDE + ni * 8 + g;
                    mma_tf32(oacc[ni], pf, vp[0], vp[4 * VS_STRIDE]);
                }
            }
        }
        __syncthreads();  // all warps done with buf before its cp.async refill
    }

    // epilogue: normalize, store to g_attn [B*S, H*DV]
    float inv0 = 1.f / l0, inv1 = 1.f / l1;
    float* d0 = g_attn + (size_t)(b * SEQ + qt * 128 + wid * 16 + g) * (NHEADS * DV) + h * DV;
    float* d1 = d0 + (size_t)8 * (NHEADS * DV);
    #pragma unroll
    for (int ni = 0; ni < 16; ni++) {
        *(float2*)(d0 + ni * 8 + 2 * t) = make_float2(oacc[ni][0] * inv0, oacc[ni][1] * inv0);
        *(float2*)(d1 + ni * 8 + 2 * t) = make_float2(oacc[ni][2] * inv1, oacc[ni][3] * inv1);
    }
}

// ---------------- launch -----------------------------------------------------
extern "C" void kernel_launch(void* const* d_in, const int* in_sizes, int n_in,
                              void* d_out, int out_size)
{
    const float* q_in = (const float*)d_in[0];
    const float* k_in = (const float*)d_in[1];
    const float* v_in = (const float*)d_in[2];
    const float* Wq = (const float*)d_in[4];
    const float* bq = (const float*)d_in[5];
    const float* Wk = (const float*)d_in[6];
    const float* bk = (const float*)d_in[7];
    const float* Wv = (const float*)d_in[8];
    const float* bv = (const float*)d_in[9];
    const float* Wo = (const float*)d_in[10];
    const float* bo = (const float*)d_in[11];
    float* out = (float*)d_out;

    float *gq, *gattn;
    cudaGetSymbolAddress((void**)&gq, g_q);
    cudaGetSymbolAddress((void**)&gattn, g_attn);

    cudaFuncSetAttribute(gemm_kernel<false>,
                         cudaFuncAttributeMaxDynamicSharedMemorySize, GEMM_SMEM);
    cudaFuncSetAttribute(gemm_kernel<true>,
                         cudaFuncAttributeMaxDynamicSharedMemorySize, GEMM_SMEM);
    cudaFuncSetAttribute(kv_split_kernel,
                         cudaFuncAttributeMaxDynamicSharedMemorySize, GEMM_SMEM);
    cudaFuncSetAttribute(flash_mma_kernel,
                         cudaFuncAttributeMaxDynamicSharedMemorySize, FA_SMEM);

    // 1) KV split-K projection (independent of rope table)
    kv_split_kernel<<<dim3(2, MROWS / 128, KV_SPLITS), 256, GEMM_SMEM>>>(k_in, v_in, Wk, Wv);

    // 2) rope table (needed by Q-gemm epilogue and K reduce)
    rope_table_kernel<<<(SEQ * 64 + 255) / 256, 256>>>();

    // 3) Q projection with fused RoPE epilogue (tf32-rounded output)
    gemm_kernel<true><<<dim3(DMODEL / 128, MROWS / 128), 256, GEMM_SMEM>>>(
        q_in, DMODEL, Wq, DMODEL, bq, gq, DMODEL, DMODEL);

    // 4-5) KV reduce: bias + K-RoPE + interleave (split so flash is launch #6)
    kv_reduce_k_kernel<<<(MROWS * 64 + 255) / 256, 256>>>(bk);
    kv_reduce_v_kernel<<<(MROWS * 128 + 255) / 256, 256>>>(bv);

    // 6) attention (HMMA tf32 flash, cp.async double-buffered) — ncu capture slot
    flash_mma_kernel<<<dim3(SEQ / 128, NHEADS, BATCH), 256, FA_SMEM>>>();

    // 7) output projection
    gemm_kernel<false><<<dim3(DMODEL / 128, MROWS / 128), 256, GEMM_SMEM>>>(
        gattn, DMODEL, Wo, DMODEL, bo, out, DMODEL, DMODEL);
}